// round 5
// baseline (speedup 1.0000x reference)
#include <cuda_runtime.h>
#include <cuda_fp16.h>
#include <cstdint>

#define DK    4096
#define NCOL  64
#define TM    128
#define KC    32
#define NIT   128            // DK / KC
#define MAX_M 16384
#define WSC   4096.0f        // 2^12 W pre-scale (exact inverse in epilogue)
#define WSCI  (1.0f / 4096.0f)

// ---------------- device scratch ----------------
// W hi/lo fp16 in m16n8k16 B-fragment layout:
// [k16:256][term:2][grp:4][lane:32][8 u16]
__device__ uint16_t     g_Whf[256 * 2 * 4 * 32 * 8];
__device__ float        g_Y[MAX_M * NCOL];
__device__ float        g_colscale[NCOL];
__device__ unsigned int g_absmax_bits;

// ---------------- helpers ----------------
__device__ __forceinline__ void cp_async16(uint32_t dst, const void* src) {
    asm volatile("cp.async.cg.shared.global [%0], [%1], 16;" :: "r"(dst), "l"(src));
}
#define CP_COMMIT() asm volatile("cp.async.commit_group;")
#define CP_WAIT0()  asm volatile("cp.async.wait_group 0;")

__device__ __forceinline__ void lds128(uint4& v, uint32_t a) {
    asm volatile("ld.shared.v4.b32 {%0,%1,%2,%3}, [%4];"
                 : "=r"(v.x), "=r"(v.y), "=r"(v.z), "=r"(v.w) : "r"(a));
}
__device__ __forceinline__ float2 lds64f(uint32_t a) {
    float2 v;
    asm volatile("ld.shared.v2.f32 {%0,%1}, [%2];" : "=f"(v.x), "=f"(v.y) : "r"(a));
    return v;
}

__device__ __forceinline__ uint32_t f16x2_rn(float a, float b) {
    uint32_t r;
    asm("cvt.rn.f16x2.f32 %0, %1, %2;" : "=r"(r) : "f"(b), "f"(a));
    return r;
}
__device__ __forceinline__ void f16x2_unpack(uint32_t p, float& lo, float& hi) {
    asm("{.reg .f16 l, h; mov.b32 {l, h}, %2;"
        " cvt.f32.f16 %0, l; cvt.f32.f16 %1, h;}"
        : "=f"(lo), "=f"(hi) : "r"(p));
}
__device__ __forceinline__ void split_pair(float2 x, uint32_t& h, uint32_t& l) {
    h = f16x2_rn(x.x, x.y);
    float hx, hy;
    f16x2_unpack(h, hx, hy);
    l = f16x2_rn(x.x - hx, x.y - hy);
}

// m16n8k16 fp16 mma, fp32 accumulate in place
__device__ __forceinline__ void mma16(float4& d, uint32_t a0, uint32_t a1,
                                      uint32_t a2, uint32_t a3,
                                      uint32_t b0, uint32_t b1) {
    asm volatile(
        "mma.sync.aligned.m16n8k16.row.col.f32.f16.f16.f32 "
        "{%0,%1,%2,%3},{%4,%5,%6,%7},{%8,%9},{%0,%1,%2,%3};"
        : "+f"(d.x), "+f"(d.y), "+f"(d.z), "+f"(d.w)
        : "r"(a0), "r"(a1), "r"(a2), "r"(a3), "r"(b0), "r"(b1));
}

// ---------------- kernel 0: rank mask + scaling ----------------
__global__ void k_prep(const float* __restrict__ ri) {
    __shared__ int cnt;
    int j = threadIdx.x;
    if (j == 0) { cnt = 0; g_absmax_bits = 0u; }
    __syncthreads();
    float s = 1.0f / (1.0f + expf(-ri[j]));
    int a = (s > 0.1f) ? 1 : 0;
    atomicAdd(&cnt, a);
    __syncthreads();
    float f = (cnt > 0) ? (float)a : 1.0f;
    g_colscale[j] = 0.25f * WSC * f;        // SCALING * 2^12 * mask
}

// ---------------- kernel 1: W=(B@A)*colscale -> fp16 hi/lo fragment layout ----
__global__ void k_w(const float* __restrict__ Bm, const float* __restrict__ A) {
    __shared__ float sA[64 * 64];
    __shared__ float sB[4 * 64];
    int tx = threadIdx.x, ty = threadIdx.y;
    int tid = ty * 64 + tx;
    int k = blockIdx.x * 4 + ty;            // 0..4095
#pragma unroll
    for (int t = 0; t < 16; t++) sA[tid + t * 256] = A[tid + t * 256];
    sB[tid] = Bm[blockIdx.x * 256 + tid];
    __syncthreads();
    float acc = 0.0f;
#pragma unroll 8
    for (int r = 0; r < 64; r++)
        acc = fmaf(sB[ty * 64 + r], sA[r * 64 + tx], acc);
    float w = acc * g_colscale[tx];

    __half hh = __float2half_rn(w);
    float  hf = __half2float(hh);
    __half hl = __float2half_rn(w - hf);

    int n = tx;
    int k16 = k >> 4, kr = k & 15;
    int reg = kr >> 3;
    int l   = ((n & 7) << 2) | ((kr & 7) >> 1);
    int grp = n >> 4;
    int ntp = (n >> 3) & 1;
    size_t base = ((((size_t)(k16 * 2 + 0) * 4 + grp) * 32 + l) * 8)
                  + (size_t)(ntp * 2 + reg) * 2 + (kr & 1);
    size_t lobase = base + (size_t)4 * 32 * 8;   // term stride
    g_Whf[base]   = __half_as_ushort(hh);
    g_Whf[lobase] = __half_as_ushort(hl);
}

// ---------------- kernel 2: Y = x @ W via mma.sync fp16 3-term ----------------
// 256 threads / 8 warps: warp (mh=wid>>1 in 0..3, nh=wid&1) owns
// rows mh*32..+31 (2 m16 tiles) x cols nh*32..+31 (4 n8 tiles).
#define SMA_SZ 18432                 // 128 rows * 144B (36-float stride)
#define SMB_SZ 8192                  // per chunk B fragments
#define SM_TOTAL (2 * SMA_SZ + 2 * SMB_SZ)

__global__ void __launch_bounds__(256, 1) k_gemm(const float* __restrict__ x) {
    extern __shared__ char smem[];
    uint32_t sbA = (uint32_t)__cvta_generic_to_shared(smem);
    uint32_t sbB = sbA + 2 * SMA_SZ;

    int tid = threadIdx.x;
    int wid = tid >> 5, l = tid & 31;
    int mh = wid >> 1, nh = wid & 1;
    int m0 = blockIdx.x * TM;
    const float* xblk = x + (size_t)m0 * DK;
    const char* wsrc = (const char*)g_Whf;

    float4 C[2][4], S[2][4];
#pragma unroll
    for (int a = 0; a < 2; a++)
#pragma unroll
        for (int b = 0; b < 4; b++) {
            C[a][b] = make_float4(0.f, 0.f, 0.f, 0.f);
            S[a][b] = make_float4(0.f, 0.f, 0.f, 0.f);
        }

    int r_in = l >> 2;       // 0..7
    int cq   = l & 3;        // 0..3

    // ---- prologue: cp chunk 0 (256 threads)
#pragma unroll
    for (int i = 0; i < 4; i++) {
        int idx = i * 256 + tid;
        int row = idx >> 3, q = idx & 7;
        cp_async16(sbA + (uint32_t)(row * 144 + q * 16),
                   xblk + (size_t)row * DK + q * 4);
    }
#pragma unroll
    for (int i = 0; i < 2; i++) {
        int idx = i * 256 + tid;
        cp_async16(sbB + (uint32_t)(idx * 16), wsrc + (size_t)idx * 16);
    }
    CP_COMMIT();

#pragma unroll 1
    for (int c = 0; c < NIT; c++) {
        int buf = c & 1;
        CP_WAIT0();
        __syncthreads();

        if (c + 1 < NIT) {
            int nb = (c + 1) & 1;
            int k0 = (c + 1) * KC;
            uint32_t aoff = sbA + (uint32_t)(nb * SMA_SZ);
            uint32_t boff = sbB + (uint32_t)(nb * SMB_SZ);
            const char* bs = wsrc + (size_t)(c + 1) * SMB_SZ;
#pragma unroll
            for (int i = 0; i < 4; i++) {
                int idx = i * 256 + tid;
                int row = idx >> 3, q = idx & 7;
                cp_async16(aoff + (uint32_t)(row * 144 + q * 16),
                           xblk + (size_t)row * DK + k0 + q * 4);
            }
#pragma unroll
            for (int i = 0; i < 2; i++) {
                int idx = i * 256 + tid;
                cp_async16(boff + (uint32_t)(idx * 16), bs + (size_t)idx * 16);
            }
            CP_COMMIT();
        }

        uint32_t ab = sbA + (uint32_t)(buf * SMA_SZ);
        uint32_t bb = sbB + (uint32_t)(buf * SMB_SZ);

#pragma unroll
        for (int ks = 0; ks < 2; ks++) {
            uint4 BH[2], BL[2];
#pragma unroll
            for (int g = 0; g < 2; g++) {
                uint32_t bh  = bb + (uint32_t)((((ks * 2 + 0) * 4 + nh * 2 + g) * 32 + l) * 16);
                uint32_t blo = bb + (uint32_t)((((ks * 2 + 1) * 4 + nh * 2 + g) * 32 + l) * 16);
                lds128(BH[g], bh);
                lds128(BL[g], blo);
            }

#pragma unroll
            for (int rt = 0; rt < 2; rt++) {
                int row = mh * 32 + rt * 16 + r_in;
                uint32_t ra = ab + (uint32_t)(row * 144 + (ks * 16 + cq * 2) * 4);
                float2 p0 = lds64f(ra);
                float2 p1 = lds64f(ra + 8 * 144);
                float2 p2 = lds64f(ra + 32);
                float2 p3 = lds64f(ra + 8 * 144 + 32);

                uint32_t ah0, al0, ah1, al1, ah2, al2, ah3, al3;
                split_pair(p0, ah0, al0);
                split_pair(p1, ah1, al1);
                split_pair(p2, ah2, al2);
                split_pair(p3, ah3, al3);

                // term-major issue order: dependency distance 4 to each acc
                mma16(C[rt][0], ah0, ah1, ah2, ah3, BH[0].x, BH[0].y);
                mma16(C[rt][1], ah0, ah1, ah2, ah3, BH[0].z, BH[0].w);
                mma16(C[rt][2], ah0, ah1, ah2, ah3, BH[1].x, BH[1].y);
                mma16(C[rt][3], ah0, ah1, ah2, ah3, BH[1].z, BH[1].w);

                mma16(C[rt][0], ah0, ah1, ah2, ah3, BL[0].x, BL[0].y);
                mma16(C[rt][1], ah0, ah1, ah2, ah3, BL[0].z, BL[0].w);
                mma16(C[rt][2], ah0, ah1, ah2, ah3, BL[1].x, BL[1].y);
                mma16(C[rt][3], ah0, ah1, ah2, ah3, BL[1].z, BL[1].w);

                mma16(C[rt][0], al0, al1, al2, al3, BH[0].x, BH[0].y);
                mma16(C[rt][1], al0, al1, al2, al3, BH[0].z, BH[0].w);
                mma16(C[rt][2], al0, al1, al2, al3, BH[1].x, BH[1].y);
                mma16(C[rt][3], al0, al1, al2, al3, BH[1].z, BH[1].w);
            }
        }

        // drain every 16 chunks (shortens fp32 accumulation chain)
        if ((c & 15) == 15) {
#pragma unroll
            for (int a = 0; a < 2; a++)
#pragma unroll
                for (int b = 0; b < 4; b++) {
                    S[a][b].x += C[a][b].x; S[a][b].y += C[a][b].y;
                    S[a][b].z += C[a][b].z; S[a][b].w += C[a][b].w;
                    C[a][b] = make_float4(0.f, 0.f, 0.f, 0.f);
                }
        }
    }

    // ---- epilogue: un-scale (exact 2^-12), store Y, abs-max
    float mx = 0.0f;
#pragma unroll
    for (int rt = 0; rt < 2; rt++)
#pragma unroll
        for (int nt = 0; nt < 4; nt++) {
            float4 v = S[rt][nt];
            v.x *= WSCI; v.y *= WSCI; v.z *= WSCI; v.w *= WSCI;
            int row = m0 + mh * 32 + rt * 16 + r_in;
            int col = nh * 32 + nt * 8 + cq * 2;
            *(float2*)&g_Y[(size_t)row * NCOL + col]       = make_float2(v.x, v.y);
            *(float2*)&g_Y[(size_t)(row + 8) * NCOL + col] = make_float2(v.z, v.w);
            mx = fmaxf(mx, fmaxf(fmaxf(fabsf(v.x), fabsf(v.y)),
                                 fmaxf(fabsf(v.z), fabsf(v.w))));
        }
#pragma unroll
    for (int off = 16; off; off >>= 1)
        mx = fmaxf(mx, __shfl_xor_sync(0xffffffffu, mx, off));
    if (l == 0) atomicMax(&g_absmax_bits, __float_as_uint(mx));
}

// ---------------- kernel 3: NF4 quantize (midpoint count) ----------------
__global__ void k_quant(float* __restrict__ out, const float* __restrict__ qs, int n4) {
    const float L[16] = {
        -1.0f, -0.6961928009986877f, -0.5250730514526367f, -0.39491748809814453f,
        -0.28444138169288635f, -0.18477343022823334f, -0.09105003625154495f, 0.0f,
        0.07958029955625534f, 0.16093020141124725f, 0.24611230194568634f,
        0.33791524171829224f, 0.44070982933044434f, 0.5626170039176941f,
        0.7229568362236023f, 1.0f };
    float MID[15];
#pragma unroll
    for (int i = 0; i < 15; i++) MID[i] = 0.5f * (L[i] + L[i + 1]);

    int i = blockIdx.x * blockDim.x + threadIdx.x;
    if (i >= n4) return;
    float absmax = __uint_as_float(g_absmax_bits);
    float qscale = qs[0];
    float4 y = ((const float4*)g_Y)[i];
    float4 o;
    if (absmax > 0.0f) {
        float inv = 1.0f / absmax;
        float v[4] = { y.x * inv, y.y * inv, y.z * inv, y.w * inv };
        float r[4];
#pragma unroll
        for (int t = 0; t < 4; t++) {
            int idx = 0;
#pragma unroll
            for (int b = 0; b < 15; b++) idx += (v[t] > MID[b]) ? 1 : 0;
            r[t] = L[idx] * absmax;
        }
        o = make_float4(r[0], r[1], r[2], r[3]);
    } else {
        o = y;
    }
    o.x *= qscale; o.y *= qscale; o.z *= qscale; o.w *= qscale;
    ((float4*)out)[i] = o;
}

// ---------------- launch ----------------
extern "C" void kernel_launch(void* const* d_in, const int* in_sizes, int n_in,
                              void* d_out, int out_size) {
    const float* x  = (const float*)d_in[0];   // [4,4096,4096]
    const float* A  = (const float*)d_in[1];   // [64,64]
    const float* Bm = (const float*)d_in[2];   // [4096,64]
    const float* qs = (const float*)d_in[3];   // [1]
    const float* ri = (const float*)d_in[4];   // [64]
    float* out = (float*)d_out;

    int M = in_sizes[0] / DK;   // 16384

    cudaFuncSetAttribute(k_gemm, cudaFuncAttributeMaxDynamicSharedMemorySize, SM_TOTAL);

    k_prep<<<1, 64>>>(ri);
    k_w<<<DK / 4, dim3(64, 4)>>>(Bm, A);
    k_gemm<<<M / TM, 256, SM_TOTAL>>>(x);
    int n4 = (M * NCOL) / 4;
    k_quant<<<(n4 + 255) / 256, 256>>>(out, qs, n4);
}